// round 2
// baseline (speedup 1.0000x reference)
#include <cuda_runtime.h>
#include <cuda_bf16.h>
#include <cstdint>
#include <math.h>

// ---------------- problem constants ----------------
#define TLEN 1024
#define HID  2048
#define NKH  8
#define NVH  16
#define QKVZN 6144
#define SCALE_Q 0.08838834764831845f   // 128^-0.5

// ---------------- device scratch (no allocation allowed) ----------------
__device__ float g_qkvz[TLEN * QKVZN];          // [t][6144]
__device__ float g_ba  [TLEN * 32];             // [t][32]
__device__ float g_q   [TLEN * 1024];           // conv+silu q  [t][kh*128+i]
__device__ float g_k   [TLEN * 1024];           // conv+silu k
__device__ float g_v   [TLEN * 2048];           // conv+silu v  [t][vh*128+i]
__device__ float g_qn  [NKH * TLEN * 128];      // [kh][t][i]  normalized*scale
__device__ float g_kn  [NKH * TLEN * 128];      // [kh][t][i]  normalized
__device__ float g_scal[NVH * TLEN * 4];        // [vh][t]{eg,beta,qk,0}
__device__ float g_o   [TLEN * 2048];           // scan output [t][vh*128+i]
__device__ float g_xn  [TLEN * 2048];           // rmsnorm output

// ---------------- helpers ----------------
__device__ __forceinline__ float to_tf32(float x) {
    float r;
    asm("cvt.rna.tf32.f32 %0, %1;" : "=f"(r) : "f"(x));
    return r;
}

__device__ __forceinline__ void cp16(void* smem_dst, const void* gmem_src) {
    uint32_t s = (uint32_t)__cvta_generic_to_shared(smem_dst);
    asm volatile("cp.async.cg.shared.global [%0], [%1], 16;\n" :: "r"(s), "l"(gmem_src));
}
#define CP_COMMIT()  asm volatile("cp.async.commit_group;\n")
#define CP_WAIT(n)   asm volatile("cp.async.wait_group %0;\n" :: "n"(n))

__device__ __forceinline__ void mma_tf32(float& d0, float& d1, float& d2, float& d3,
                                         uint32_t a0, uint32_t a1, uint32_t a2, uint32_t a3,
                                         uint32_t b0, uint32_t b1) {
    asm volatile(
        "mma.sync.aligned.m16n8k8.row.col.f32.tf32.tf32.f32 "
        "{%0,%1,%2,%3},{%4,%5,%6,%7},{%8,%9},{%0,%1,%2,%3};"
        : "+f"(d0), "+f"(d1), "+f"(d2), "+f"(d3)
        : "r"(a0), "r"(a1), "r"(a2), "r"(a3), "r"(b0), "r"(b1));
}

// ================= tf32 GEMM: C[M,N] = A[M,K] * B[N,K]^T =================
// BM=128, BN=128, BK=16, 256 threads (8 warps, each 64x32)
__global__ __launch_bounds__(256, 1)
void gemm_tf32(const float* __restrict__ A, const float* __restrict__ B,
               float* __restrict__ C, int M, int N, int K) {
    __shared__ float sA[2][128 * 20];
    __shared__ float sB[2][128 * 20];

    const int tid  = threadIdx.x;
    const int warp = tid >> 5, lane = tid & 31;
    const int wm = warp & 1, wn = warp >> 1;           // 2 x 4 warp grid
    const int bm = blockIdx.y * 128, bn = blockIdx.x * 128;

    const float* Ab = A + (size_t)bm * K;
    const float* Bb = B + (size_t)bn * K;

    const int r0  = tid >> 2;       // 0..63
    const int c4  = tid & 3;        // 0..3 (float4 column)

    float acc[4][4][4];
#pragma unroll
    for (int i = 0; i < 4; i++)
#pragma unroll
        for (int j = 0; j < 4; j++)
#pragma unroll
            for (int l = 0; l < 4; l++) acc[i][j][l] = 0.f;

    const int nk = K >> 4;  // tiles of BK=16

    float4 ar0, ar1, br0, br1;
    {
        const float* pa = Ab + (size_t)r0 * K + c4 * 4;
        ar0 = *(const float4*)(pa);
        ar1 = *(const float4*)(pa + (size_t)64 * K);
        const float* pb = Bb + (size_t)r0 * K + c4 * 4;
        br0 = *(const float4*)(pb);
        br1 = *(const float4*)(pb + (size_t)64 * K);
    }

    for (int kt = 0; kt < nk; kt++) {
        const int buf = kt & 1;
        // store (with tf32 round) to smem
        {
            float4 t;
            t.x = to_tf32(ar0.x); t.y = to_tf32(ar0.y); t.z = to_tf32(ar0.z); t.w = to_tf32(ar0.w);
            *(float4*)&sA[buf][r0 * 20 + c4 * 4] = t;
            t.x = to_tf32(ar1.x); t.y = to_tf32(ar1.y); t.z = to_tf32(ar1.z); t.w = to_tf32(ar1.w);
            *(float4*)&sA[buf][(r0 + 64) * 20 + c4 * 4] = t;
            t.x = to_tf32(br0.x); t.y = to_tf32(br0.y); t.z = to_tf32(br0.z); t.w = to_tf32(br0.w);
            *(float4*)&sB[buf][r0 * 20 + c4 * 4] = t;
            t.x = to_tf32(br1.x); t.y = to_tf32(br1.y); t.z = to_tf32(br1.z); t.w = to_tf32(br1.w);
            *(float4*)&sB[buf][(r0 + 64) * 20 + c4 * 4] = t;
        }
        __syncthreads();

        if (kt + 1 < nk) {
            const int k0 = (kt + 1) << 4;
            const float* pa = Ab + (size_t)r0 * K + k0 + c4 * 4;
            ar0 = *(const float4*)(pa);
            ar1 = *(const float4*)(pa + (size_t)64 * K);
            const float* pb = Bb + (size_t)r0 * K + k0 + c4 * 4;
            br0 = *(const float4*)(pb);
            br1 = *(const float4*)(pb + (size_t)64 * K);
        }

        const float* sAb = &sA[buf][0];
        const float* sBb = &sB[buf][0];
#pragma unroll
        for (int ks = 0; ks < 2; ks++) {
            uint32_t af[4][4];
#pragma unroll
            for (int mt = 0; mt < 4; mt++) {
                const float* p = sAb + (wm * 64 + mt * 16 + (lane >> 2)) * 20 + ks * 8 + (lane & 3);
                af[mt][0] = __float_as_uint(p[0]);
                af[mt][1] = __float_as_uint(p[8 * 20]);
                af[mt][2] = __float_as_uint(p[4]);
                af[mt][3] = __float_as_uint(p[8 * 20 + 4]);
            }
            uint32_t bf[4][2];
#pragma unroll
            for (int nt = 0; nt < 4; nt++) {
                const float* p = sBb + (wn * 32 + nt * 8 + (lane >> 2)) * 20 + ks * 8 + (lane & 3);
                bf[nt][0] = __float_as_uint(p[0]);
                bf[nt][1] = __float_as_uint(p[4]);
            }
#pragma unroll
            for (int mt = 0; mt < 4; mt++)
#pragma unroll
                for (int nt = 0; nt < 4; nt++)
                    mma_tf32(acc[mt][nt][0], acc[mt][nt][1], acc[mt][nt][2], acc[mt][nt][3],
                             af[mt][0], af[mt][1], af[mt][2], af[mt][3],
                             bf[nt][0], bf[nt][1]);
        }
    }

    // writeback
#pragma unroll
    for (int mt = 0; mt < 4; mt++) {
#pragma unroll
        for (int nt = 0; nt < 4; nt++) {
            int row = bm + wm * 64 + mt * 16 + (lane >> 2);
            int col = bn + wn * 32 + nt * 8 + (lane & 3) * 2;
            C[(size_t)row * N + col]           = acc[mt][nt][0];
            C[(size_t)row * N + col + 1]       = acc[mt][nt][1];
            C[(size_t)(row + 8) * N + col]     = acc[mt][nt][2];
            C[(size_t)(row + 8) * N + col + 1] = acc[mt][nt][3];
        }
    }
}

// ================= ba projection: [1024,32] = hs @ w_ba^T =================
__global__ __launch_bounds__(256)
void ba_kernel(const float* __restrict__ hs, const float* __restrict__ wba,
               float* __restrict__ out) {
    const int t = blockIdx.x;
    const int tid = threadIdx.x;
    const int n = tid >> 3, s = tid & 7;
    const float4* h4 = (const float4*)(hs + (size_t)t * HID + s * 256);
    const float4* w4 = (const float4*)(wba + (size_t)n * HID + s * 256);
    float acc = 0.f;
#pragma unroll 8
    for (int i = 0; i < 64; i++) {
        float4 a = h4[i], b = w4[i];
        acc += a.x * b.x + a.y * b.y + a.z * b.z + a.w * b.w;
    }
    acc += __shfl_xor_sync(0xffffffffu, acc, 1);
    acc += __shfl_xor_sync(0xffffffffu, acc, 2);
    acc += __shfl_xor_sync(0xffffffffu, acc, 4);
    if (s == 0) out[t * 32 + n] = acc;
}

// ================= depthwise causal conv1d + silu =================
// grid (32 channel-blocks, 32 t-blocks), 256 threads
__global__ __launch_bounds__(256)
void conv_kernel(const float* __restrict__ qkvz, const float* __restrict__ convw,
                 float* __restrict__ gq, float* __restrict__ gk, float* __restrict__ gv) {
    const int cb = blockIdx.x;
    const int t0 = blockIdx.y * 32;
    __shared__ float sx[35][128];

    int colbase;
    const int chbase = cb * 128;
    if (cb < 8)        colbase = cb * 768;
    else if (cb < 16)  colbase = (cb - 8) * 768 + 128;
    else { int vh = cb - 16; colbase = (vh >> 1) * 768 + 256 + (vh & 1) * 128; }

    for (int idx = threadIdx.x; idx < 35 * 128; idx += 256) {
        const int r = idx >> 7, c = idx & 127;
        const int t = t0 + r - 3;
        sx[r][c] = (t >= 0) ? qkvz[(size_t)t * QKVZN + colbase + c] : 0.f;
    }
    __syncthreads();

    for (int idx = threadIdx.x; idx < 32 * 128; idx += 256) {
        const int r = idx >> 7, c = idx & 127;
        const int ch = chbase + c;
        const float4 w = *(const float4*)(convw + ch * 4);
        float y = sx[r][c] * w.x + sx[r + 1][c] * w.y + sx[r + 2][c] * w.z + sx[r + 3][c] * w.w;
        y = y / (1.f + expf(-y));  // silu
        const int t = t0 + r;
        if (ch < 1024)      gq[t * 1024 + ch] = y;
        else if (ch < 2048) gk[t * 1024 + ch - 1024] = y;
        else                gv[t * 2048 + ch - 2048] = y;
    }
}

// ================= prep: l2-norm q,k, qk dot, gates =================
// grid (1024, 8), 128 threads
__global__ __launch_bounds__(128)
void prep_kernel(const float* __restrict__ gq, const float* __restrict__ gk,
                 const float* __restrict__ gba, const float* __restrict__ A_log,
                 const float* __restrict__ dt_bias,
                 float* __restrict__ gqn, float* __restrict__ gkn,
                 float* __restrict__ gscal) {
    const int t = blockIdx.x, kh = blockIdx.y, i = threadIdx.x;
    __shared__ float red[4];

    const float q = gq[t * 1024 + kh * 128 + i];
    const float k = gk[t * 1024 + kh * 128 + i];

    // reduce helper (inlined 3x)
    float v, s_qq, s_kk, s_qk;

    v = q * q;
#pragma unroll
    for (int m = 16; m; m >>= 1) v += __shfl_xor_sync(0xffffffffu, v, m);
    if ((i & 31) == 0) red[i >> 5] = v;
    __syncthreads();
    s_qq = red[0] + red[1] + red[2] + red[3];
    __syncthreads();

    v = k * k;
#pragma unroll
    for (int m = 16; m; m >>= 1) v += __shfl_xor_sync(0xffffffffu, v, m);
    if ((i & 31) == 0) red[i >> 5] = v;
    __syncthreads();
    s_kk = red[0] + red[1] + red[2] + red[3];
    __syncthreads();

    const float qn = q * rsqrtf(s_qq + 1e-6f) * SCALE_Q;
    const float kn = k * rsqrtf(s_kk + 1e-6f);
    gqn[((size_t)kh * TLEN + t) * 128 + i] = qn;
    gkn[((size_t)kh * TLEN + t) * 128 + i] = kn;

    v = qn * kn;
#pragma unroll
    for (int m = 16; m; m >>= 1) v += __shfl_xor_sync(0xffffffffu, v, m);
    if ((i & 31) == 0) red[i >> 5] = v;
    __syncthreads();
    s_qk = red[0] + red[1] + red[2] + red[3];

    if (i < 2) {
        const int vh = kh * 2 + i;
        const float b = gba[t * 32 + kh * 4 + i];
        const float a = gba[t * 32 + kh * 4 + 2 + i];
        const float beta = 1.f / (1.f + expf(-b));
        const float x = a + dt_bias[vh];
        const float sp = (x > 20.f) ? x : log1pf(expf(x));
        const float g = -expf(A_log[vh]) * sp;
        float4 sc;
        sc.x = expf(g); sc.y = beta; sc.z = s_qk; sc.w = 0.f;
        *(float4*)(gscal + ((size_t)vh * TLEN + t) * 4) = sc;
    }
}

// ================= gated delta-rule scan =================
// grid (8 vblocks, 16 heads), 128 threads = 8 kgroups x 16 vcols
__global__ __launch_bounds__(128, 1)
void scan_kernel(const float* __restrict__ gqn, const float* __restrict__ gkn,
                 const float* __restrict__ gv, const float* __restrict__ gscal,
                 float* __restrict__ go) {
    const int vb = blockIdx.x;    // 0..7
    const int vh = blockIdx.y;    // 0..15
    const int kh = vh >> 1;
    const int tid = threadIdx.x;
    const int kg = tid & 7;       // k group (16 k-slots each)
    const int vc = tid >> 3;      // v col within block (0..15)

    __shared__ float ring[8][276];  // per slot: k[128], q[128], v[16], scal[4]

    const float* kbase = gkn + (size_t)kh * TLEN * 128;
    const float* qbase = gqn + (size_t)kh * TLEN * 128;
    const float* vbase = gv + vh * 128 + vb * 16;
    const float* sbase = gscal + (size_t)vh * TLEN * 4;

    float S[16];
#pragma unroll
    for (int i = 0; i < 16; i++) S[i] = 0.f;

    auto prefetch = [&](int tt) {
        if (tt < TLEN) {
            float* sl = ring[tt & 7];
            if (tid < 32)       cp16(sl + tid * 4, kbase + (size_t)tt * 128 + tid * 4);
            else if (tid < 64)  cp16(sl + 128 + (tid - 32) * 4, qbase + (size_t)tt * 128 + (tid - 32) * 4);
            else if (tid < 68)  cp16(sl + 256 + (tid - 64) * 4, vbase + (size_t)tt * 2048 + (tid - 64) * 4);
            else if (tid == 68) cp16(sl + 272, sbase + (size_t)tt * 4);
        }
        CP_COMMIT();
    };

    for (int p = 0; p < 6; p++) prefetch(p);

    const int obase = vh * 128 + vb * 16 + vc;

    for (int t = 0; t < TLEN; t += 2) {
        CP_WAIT(4);
        __syncthreads();
#pragma unroll
        for (int u = 0; u < 2; u++) {
            const int tt = t + u;
            const float* sl = ring[tt & 7];
            float4 kk[4], qq[4];
            const float4* kp = (const float4*)(sl + kg * 16);
            const float4* qp = (const float4*)(sl + 128 + kg * 16);
#pragma unroll
            for (int j = 0; j < 4; j++) { kk[j] = kp[j]; qq[j] = qp[j]; }

            // split accumulation chains for ILP
            float r1a = 0.f, r1b = 0.f, r2a = 0.f, r2b = 0.f;
#pragma unroll
            for (int j = 0; j < 2; j++) {
                r1a += kk[j].x * S[j * 4 + 0]; r2a += qq[j].x * S[j * 4 + 0];
                r1a += kk[j].y * S[j * 4 + 1]; r2a += qq[j].y * S[j * 4 + 1];
                r1a += kk[j].z * S[j * 4 + 2]; r2a += qq[j].z * S[j * 4 + 2];
                r1a += kk[j].w * S[j * 4 + 3]; r2a += qq[j].w * S[j * 4 + 3];
            }
#pragma unroll
            for (int j = 2; j < 4; j++) {
                r1b += kk[j].x * S[j * 4 + 0]; r2b += qq[j].x * S[j * 4 + 0];
                r1b += kk[j].y * S[j * 4 + 1]; r2b += qq[j].y * S[j * 4 + 1];
                r1b += kk[j].z * S[j * 4 + 2]; r2b += qq[j].z * S[j * 4 + 2];
                r1b += kk[j].w * S[j * 4 + 3]; r2b += qq[j].w * S[j * 4 + 3];
            }
            float r1 = r1a + r1b, r2 = r2a + r2b;
            r1 += __shfl_xor_sync(0xffffffffu, r1, 1);
            r2 += __shfl_xor_sync(0xffffffffu, r2, 1);
            r1 += __shfl_xor_sync(0xffffffffu, r1, 2);
            r2 += __shfl_xor_sync(0xffffffffu, r2, 2);
            r1 += __shfl_xor_sync(0xffffffffu, r1, 4);
            r2 += __shfl_xor_sync(0xffffffffu, r2, 4);

            const float eg = sl[272], beta = sl[273], qk = sl[274];
            const float vt = sl[256 + vc];
            const float delta = (vt - eg * r1) * beta;
            if (kg == 0) go[(size_t)tt * 2048 + obase] = eg * r2 + qk * delta;
#pragma unroll
            for (int j = 0; j < 4; j++) {
                S[j * 4 + 0] = eg * S[j * 4 + 0] + kk[j].x * delta;
                S[j * 4 + 1] = eg * S[j * 4 + 1] + kk[j].y * delta;
                S[j * 4 + 2] = eg * S[j * 4 + 2] + kk[j].z * delta;
                S[j * 4 + 3] = eg * S[j * 4 + 3] + kk[j].w * delta;
            }
        }
        prefetch(t + 6);
        prefetch(t + 7);
    }
}

// ================= gated RMSNorm =================
// grid (1024, 16), 128 threads
__global__ __launch_bounds__(128)
void rmsnorm_kernel(const float* __restrict__ go, const float* __restrict__ qkvz,
                    const float* __restrict__ nw, float* __restrict__ gxn) {
    const int t = blockIdx.x, vh = blockIdx.y, i = threadIdx.x;
    __shared__ float red[4];
    const float o = go[(size_t)t * 2048 + vh * 128 + i];
    const float z = qkvz[(size_t)t * QKVZN + (vh >> 1) * 768 + 512 + (vh & 1) * 128 + i];
    const float xf = o * (z / (1.f + expf(-z)));
    float v = xf * xf;
#pragma unroll
    for (int m = 16; m; m >>= 1) v += __shfl_xor_sync(0xffffffffu, v, m);
    if ((i & 31) == 0) red[i >> 5] = v;
    __syncthreads();
    const float s = red[0] + red[1] + red[2] + red[3];
    gxn[(size_t)t * 2048 + vh * 128 + i] = xf * rsqrtf(s * (1.f / 128.f) + 1e-6f) * nw[i];
}

// ================= launch =================
extern "C" void kernel_launch(void* const* d_in, const int* in_sizes, int n_in,
                              void* d_out, int out_size) {
    const float* hs      = (const float*)d_in[0];  // [1,1024,2048]
    const float* w_qkvz  = (const float*)d_in[1];  // [6144,2048]
    const float* w_ba    = (const float*)d_in[2];  // [32,2048]
    const float* conv_w  = (const float*)d_in[3];  // [4096,4]
    const float* dt_bias = (const float*)d_in[4];  // [16]
    const float* A_log   = (const float*)d_in[5];  // [16]
    const float* norm_w  = (const float*)d_in[6];  // [128]
    const float* w_out   = (const float*)d_in[7];  // [2048,2048]
    float* out = (float*)d_out;

    float *p_qkvz, *p_ba, *p_q, *p_k, *p_v, *p_qn, *p_kn, *p_scal, *p_o, *p_xn;
    cudaGetSymbolAddress((void**)&p_qkvz, g_qkvz);
    cudaGetSymbolAddress((void**)&p_ba,   g_ba);
    cudaGetSymbolAddress((void**)&p_q,    g_q);
    cudaGetSymbolAddress((void**)&p_k,    g_k);
    cudaGetSymbolAddress((void**)&p_v,    g_v);
    cudaGetSymbolAddress((void**)&p_qn,   g_qn);
    cudaGetSymbolAddress((void**)&p_kn,   g_kn);
    cudaGetSymbolAddress((void**)&p_scal, g_scal);
    cudaGetSymbolAddress((void**)&p_o,    g_o);
    cudaGetSymbolAddress((void**)&p_xn,   g_xn);

    // 1. qkvz projection [1024,6144]
    gemm_tf32<<<dim3(QKVZN / 128, TLEN / 128), 256>>>(hs, w_qkvz, p_qkvz, TLEN, QKVZN, HID);
    // 2. ba projection [1024,32]
    ba_kernel<<<TLEN, 256>>>(hs, w_ba, p_ba);
    // 3. conv + silu
    conv_kernel<<<dim3(32, 32), 256>>>(p_qkvz, conv_w, p_q, p_k, p_v);
    // 4. norm + gates
    prep_kernel<<<dim3(TLEN, NKH), 128>>>(p_q, p_k, p_ba, A_log, dt_bias, p_qn, p_kn, p_scal);
    // 5. delta-rule scan
    scan_kernel<<<dim3(8, NVH), 128>>>(p_qn, p_kn, p_v, p_scal, p_o);
    // 6. gated rmsnorm
    rmsnorm_kernel<<<dim3(TLEN, NVH), 128>>>(p_o, p_qkvz, norm_w, p_xn);
    // 7. output projection [1024,2048]
    gemm_tf32<<<dim3(HID / 128, TLEN / 128), 256>>>(p_xn, w_out, out, TLEN, HID, HID);
}

// round 4
// speedup vs baseline: 1.1557x; 1.1557x over previous
#include <cuda_runtime.h>
#include <cstdint>
#include <math.h>

// ---------------- problem constants ----------------
#define TLEN 1024
#define HID  2048
#define NKH  8
#define NVH  16
#define QKVZN 6144
#define SCALE_Q 0.08838834764831845f   // 128^-0.5

// ---------------- device scratch (no allocation allowed) ----------------
__device__ float g_qkvz[TLEN * QKVZN];
__device__ float g_ba  [TLEN * 32];
__device__ float g_q   [TLEN * 1024];
__device__ float g_k   [TLEN * 1024];
__device__ float g_v   [TLEN * 2048];
__device__ float g_qn  [NKH * TLEN * 128];
__device__ float g_kn  [NKH * TLEN * 128];
__device__ float g_scal[NVH * TLEN * 4];
__device__ float g_o   [TLEN * 2048];
__device__ float g_xn  [TLEN * 2048];
__device__ float g_hsr [TLEN * HID];        // tf32-rounded hidden states
__device__ float g_wqr [QKVZN * HID];       // tf32-rounded w_qkvz
__device__ float g_wor [HID * HID];         // tf32-rounded w_out

// ---------------- helpers ----------------
__device__ __forceinline__ float to_tf32(float x) {
    float r;
    asm("cvt.rna.tf32.f32 %0, %1;" : "=f"(r) : "f"(x));
    return r;
}

__device__ __forceinline__ void cp16(void* smem_dst, const void* gmem_src) {
    uint32_t s = (uint32_t)__cvta_generic_to_shared(smem_dst);
    asm volatile("cp.async.cg.shared.global [%0], [%1], 16;\n" :: "r"(s), "l"(gmem_src));
}
#define CP_COMMIT()  asm volatile("cp.async.commit_group;\n")
#define CP_WAIT(n)   asm volatile("cp.async.wait_group %0;\n" :: "n"(n))

__device__ __forceinline__ void mma_tf32(float& d0, float& d1, float& d2, float& d3,
                                         uint32_t a0, uint32_t a1, uint32_t a2, uint32_t a3,
                                         uint32_t b0, uint32_t b1) {
    asm volatile(
        "mma.sync.aligned.m16n8k8.row.col.f32.tf32.tf32.f32 "
        "{%0,%1,%2,%3},{%4,%5,%6,%7},{%8,%9},{%0,%1,%2,%3};"
        : "+f"(d0), "+f"(d1), "+f"(d2), "+f"(d3)
        : "r"(a0), "r"(a1), "r"(a2), "r"(a3), "r"(b0), "r"(b1));
}

// ================= tf32 pre-round =================
__global__ __launch_bounds__(256)
void round_tf32_k(const float4* __restrict__ in, float4* __restrict__ out, int n4) {
    int i = blockIdx.x * blockDim.x + threadIdx.x;
    const int stride = gridDim.x * blockDim.x;
    for (; i < n4; i += stride) {
        float4 v = in[i];
        v.x = to_tf32(v.x); v.y = to_tf32(v.y); v.z = to_tf32(v.z); v.w = to_tf32(v.w);
        out[i] = v;
    }
}

// ================= tf32 GEMM (cp.async 4-stage): C[M,N] = A[M,K]*B[N,K]^T =======
// BM=BN=128, BK=16, 256 threads (8 warps, each 64x32). Inputs pre-rounded to tf32.
// Stage layout: 5120 floats = A[128][20] then B[128][20] (pad-20 rows, 16B aligned).
#define GSTG 4
#define GSTF 5120
__global__ __launch_bounds__(256, 2)
void gemm_tf32_pipe(const float* __restrict__ A, const float* __restrict__ B,
                    float* __restrict__ C, int N, int K) {
    extern __shared__ float sm[];   // GSTG * GSTF floats = 80KB

    const int tid  = threadIdx.x;
    const int warp = tid >> 5, lane = tid & 31;
    const int wm = warp & 1, wn = warp >> 1;           // 2 x 4 warp grid
    const int bm = blockIdx.y * 128, bn = blockIdx.x * 128;
    const int r0 = tid >> 2, c4 = tid & 3;

    const float* Ab = A + (size_t)bm * K;
    const float* Bb = B + (size_t)bn * K;
    const int nk = K >> 4;

    float acc[4][4][4];
#pragma unroll
    for (int i = 0; i < 4; i++)
#pragma unroll
        for (int j = 0; j < 4; j++)
#pragma unroll
            for (int l = 0; l < 4; l++) acc[i][j][l] = 0.f;

    auto preload = [&](int kt) {
        const int k0 = (kt << 4) + c4 * 4;
        float* st = sm + (kt & 3) * GSTF;
        cp16(st + r0 * 20 + c4 * 4,                Ab + (size_t)r0 * K + k0);
        cp16(st + (r0 + 64) * 20 + c4 * 4,         Ab + (size_t)(r0 + 64) * K + k0);
        cp16(st + 2560 + r0 * 20 + c4 * 4,         Bb + (size_t)r0 * K + k0);
        cp16(st + 2560 + (r0 + 64) * 20 + c4 * 4,  Bb + (size_t)(r0 + 64) * K + k0);
    };

    preload(0); CP_COMMIT();
    preload(1); CP_COMMIT();
    preload(2); CP_COMMIT();

    for (int kt = 0; kt < nk; kt++) {
        CP_WAIT(2);
        __syncthreads();
        const float* sAb = sm + (kt & 3) * GSTF;
        const float* sBb = sAb + 2560;
#pragma unroll
        for (int ks = 0; ks < 2; ks++) {
            uint32_t af[4][4];
#pragma unroll
            for (int mt = 0; mt < 4; mt++) {
                const float* p = sAb + (wm * 64 + mt * 16 + (lane >> 2)) * 20 + ks * 8 + (lane & 3);
                af[mt][0] = __float_as_uint(p[0]);
                af[mt][1] = __float_as_uint(p[8 * 20]);
                af[mt][2] = __float_as_uint(p[4]);
                af[mt][3] = __float_as_uint(p[8 * 20 + 4]);
            }
            uint32_t bf[4][2];
#pragma unroll
            for (int nt = 0; nt < 4; nt++) {
                const float* p = sBb + (wn * 32 + nt * 8 + (lane >> 2)) * 20 + ks * 8 + (lane & 3);
                bf[nt][0] = __float_as_uint(p[0]);
                bf[nt][1] = __float_as_uint(p[4]);
            }
#pragma unroll
            for (int mt = 0; mt < 4; mt++)
#pragma unroll
                for (int nt = 0; nt < 4; nt++)
                    mma_tf32(acc[mt][nt][0], acc[mt][nt][1], acc[mt][nt][2], acc[mt][nt][3],
                             af[mt][0], af[mt][1], af[mt][2], af[mt][3],
                             bf[nt][0], bf[nt][1]);
        }
        if (kt + 3 < nk) preload(kt + 3);
        CP_COMMIT();
    }

    // writeback
#pragma unroll
    for (int mt = 0; mt < 4; mt++) {
#pragma unroll
        for (int nt = 0; nt < 4; nt++) {
            int row = bm + wm * 64 + mt * 16 + (lane >> 2);
            int col = bn + wn * 32 + nt * 8 + (lane & 3) * 2;
            C[(size_t)row * N + col]           = acc[mt][nt][0];
            C[(size_t)row * N + col + 1]       = acc[mt][nt][1];
            C[(size_t)(row + 8) * N + col]     = acc[mt][nt][2];
            C[(size_t)(row + 8) * N + col + 1] = acc[mt][nt][3];
        }
    }
}

// ================= ba projection: [1024,32] = hs @ w_ba^T =================
__global__ __launch_bounds__(256)
void ba_kernel(const float* __restrict__ hs, const float* __restrict__ wba,
               float* __restrict__ out) {
    const int t = blockIdx.x;
    const int tid = threadIdx.x;
    const int n = tid >> 3, s = tid & 7;
    const float4* h4 = (const float4*)(hs + (size_t)t * HID + s * 256);
    const float4* w4 = (const float4*)(wba + (size_t)n * HID + s * 256);
    float acc = 0.f;
#pragma unroll 8
    for (int i = 0; i < 64; i++) {
        float4 a = h4[i], b = w4[i];
        acc += a.x * b.x + a.y * b.y + a.z * b.z + a.w * b.w;
    }
    acc += __shfl_xor_sync(0xffffffffu, acc, 1);
    acc += __shfl_xor_sync(0xffffffffu, acc, 2);
    acc += __shfl_xor_sync(0xffffffffu, acc, 4);
    if (s == 0) out[t * 32 + n] = acc;
}

// ================= depthwise causal conv1d + silu =================
__global__ __launch_bounds__(256)
void conv_kernel(const float* __restrict__ qkvz, const float* __restrict__ convw,
                 float* __restrict__ gq, float* __restrict__ gk, float* __restrict__ gv) {
    const int cb = blockIdx.x;
    const int t0 = blockIdx.y * 32;
    __shared__ float sx[35][128];

    int colbase;
    const int chbase = cb * 128;
    if (cb < 8)        colbase = cb * 768;
    else if (cb < 16)  colbase = (cb - 8) * 768 + 128;
    else { int vh = cb - 16; colbase = (vh >> 1) * 768 + 256 + (vh & 1) * 128; }

    for (int idx = threadIdx.x; idx < 35 * 128; idx += 256) {
        const int r = idx >> 7, c = idx & 127;
        const int t = t0 + r - 3;
        sx[r][c] = (t >= 0) ? qkvz[(size_t)t * QKVZN + colbase + c] : 0.f;
    }
    __syncthreads();

    for (int idx = threadIdx.x; idx < 32 * 128; idx += 256) {
        const int r = idx >> 7, c = idx & 127;
        const int ch = chbase + c;
        const float4 w = *(const float4*)(convw + ch * 4);
        float y = sx[r][c] * w.x + sx[r + 1][c] * w.y + sx[r + 2][c] * w.z + sx[r + 3][c] * w.w;
        y = y / (1.f + expf(-y));
        const int t = t0 + r;
        if (ch < 1024)      gq[t * 1024 + ch] = y;
        else if (ch < 2048) gk[t * 1024 + ch - 1024] = y;
        else                gv[t * 2048 + ch - 2048] = y;
    }
}

// ================= prep: l2-norm q,k, qk dot, gates =================
__global__ __launch_bounds__(128)
void prep_kernel(const float* __restrict__ gq, const float* __restrict__ gk,
                 const float* __restrict__ gba, const float* __restrict__ A_log,
                 const float* __restrict__ dt_bias,
                 float* __restrict__ gqn, float* __restrict__ gkn,
                 float* __restrict__ gscal) {
    const int t = blockIdx.x, kh = blockIdx.y, i = threadIdx.x;
    __shared__ float red[4];

    const float q = gq[t * 1024 + kh * 128 + i];
    const float k = gk[t * 1024 + kh * 128 + i];

    float v, s_qq, s_kk, s_qk;

    v = q * q;
#pragma unroll
    for (int m = 16; m; m >>= 1) v += __shfl_xor_sync(0xffffffffu, v, m);
    if ((i & 31) == 0) red[i >> 5] = v;
    __syncthreads();
    s_qq = red[0] + red[1] + red[2] + red[3];
    __syncthreads();

    v = k * k;
#pragma unroll
    for (int m = 16; m; m >>= 1) v += __shfl_xor_sync(0xffffffffu, v, m);
    if ((i & 31) == 0) red[i >> 5] = v;
    __syncthreads();
    s_kk = red[0] + red[1] + red[2] + red[3];
    __syncthreads();

    const float qn = q * rsqrtf(s_qq + 1e-6f) * SCALE_Q;
    const float kn = k * rsqrtf(s_kk + 1e-6f);
    gqn[((size_t)kh * TLEN + t) * 128 + i] = qn;
    gkn[((size_t)kh * TLEN + t) * 128 + i] = kn;

    v = qn * kn;
#pragma unroll
    for (int m = 16; m; m >>= 1) v += __shfl_xor_sync(0xffffffffu, v, m);
    if ((i & 31) == 0) red[i >> 5] = v;
    __syncthreads();
    s_qk = red[0] + red[1] + red[2] + red[3];

    if (i < 2) {
        const int vh = kh * 2 + i;
        const float b = gba[t * 32 + kh * 4 + i];
        const float a = gba[t * 32 + kh * 4 + 2 + i];
        const float beta = 1.f / (1.f + expf(-b));
        const float x = a + dt_bias[vh];
        const float sp = (x > 20.f) ? x : log1pf(expf(x));
        const float g = -expf(A_log[vh]) * sp;
        float4 sc;
        sc.x = expf(g); sc.y = beta; sc.z = s_qk; sc.w = 0.f;
        *(float4*)(gscal + ((size_t)vh * TLEN + t) * 4) = sc;
    }
}

// ================= gated delta-rule scan =================
__global__ __launch_bounds__(128, 1)
void scan_kernel(const float* __restrict__ gqn, const float* __restrict__ gkn,
                 const float* __restrict__ gv, const float* __restrict__ gscal,
                 float* __restrict__ go) {
    const int vb = blockIdx.x;
    const int vh = blockIdx.y;
    const int kh = vh >> 1;
    const int tid = threadIdx.x;
    const int kg = tid & 7;
    const int vc = tid >> 3;

    __shared__ float ring[8][276];

    const float* kbase = gkn + (size_t)kh * TLEN * 128;
    const float* qbase = gqn + (size_t)kh * TLEN * 128;
    const float* vbase = gv + vh * 128 + vb * 16;
    const float* sbase = gscal + (size_t)vh * TLEN * 4;

    float S[16];
#pragma unroll
    for (int i = 0; i < 16; i++) S[i] = 0.f;

    auto prefetch = [&](int tt) {
        if (tt < TLEN) {
            float* sl = ring[tt & 7];
            if (tid < 32)       cp16(sl + tid * 4, kbase + (size_t)tt * 128 + tid * 4);
            else if (tid < 64)  cp16(sl + 128 + (tid - 32) * 4, qbase + (size_t)tt * 128 + (tid - 32) * 4);
            else if (tid < 68)  cp16(sl + 256 + (tid - 64) * 4, vbase + (size_t)tt * 2048 + (tid - 64) * 4);
            else if (tid == 68) cp16(sl + 272, sbase + (size_t)tt * 4);
        }
        CP_COMMIT();
    };

    for (int p = 0; p < 6; p++) prefetch(p);

    const int obase = vh * 128 + vb * 16 + vc;

    for (int t = 0; t < TLEN; t += 2) {
        CP_WAIT(4);
        __syncthreads();
#pragma unroll
        for (int u = 0; u < 2; u++) {
            const int tt = t + u;
            const float* sl = ring[tt & 7];
            float4 kk[4], qq[4];
            const float4* kp = (const float4*)(sl + kg * 16);
            const float4* qp = (const float4*)(sl + 128 + kg * 16);
#pragma unroll
            for (int j = 0; j < 4; j++) { kk[j] = kp[j]; qq[j] = qp[j]; }

            float r1a = 0.f, r1b = 0.f, r2a = 0.f, r2b = 0.f;
#pragma unroll
            for (int j = 0; j < 2; j++) {
                r1a += kk[j].x * S[j * 4 + 0]; r2a += qq[j].x * S[j * 4 + 0];
                r1a += kk[j].y * S[j * 4 + 1]; r2a += qq[j].y * S[j * 4 + 1];
                r1a += kk[j].z * S[j * 4 + 2]; r2a += qq[j].z * S[j * 4 + 2];
                r1a += kk[j].w * S[j * 4 + 3]; r2a += qq[j].w * S[j * 4 + 3];
            }
#pragma unroll
            for (int j = 2; j < 4; j++) {
                r1b += kk[j].x * S[j * 4 + 0]; r2b += qq[j].x * S[j * 4 + 0];
                r1b += kk[j].y * S[j * 4 + 1]; r2b += qq[j].y * S[j * 4 + 1];
                r1b += kk[j].z * S[j * 4 + 2]; r2b += qq[j].z * S[j * 4 + 2];
                r1b += kk[j].w * S[j * 4 + 3]; r2b += qq[j].w * S[j * 4 + 3];
            }
            float r1 = r1a + r1b, r2 = r2a + r2b;
            r1 += __shfl_xor_sync(0xffffffffu, r1, 1);
            r2 += __shfl_xor_sync(0xffffffffu, r2, 1);
            r1 += __shfl_xor_sync(0xffffffffu, r1, 2);
            r2 += __shfl_xor_sync(0xffffffffu, r2, 2);
            r1 += __shfl_xor_sync(0xffffffffu, r1, 4);
            r2 += __shfl_xor_sync(0xffffffffu, r2, 4);

            const float eg = sl[272], beta = sl[273], qk = sl[274];
            const float vt = sl[256 + vc];
            const float delta = (vt - eg * r1) * beta;
            if (kg == 0) go[(size_t)tt * 2048 + obase] = eg * r2 + qk * delta;
#pragma unroll
            for (int j = 0; j < 4; j++) {
                S[j * 4 + 0] = eg * S[j * 4 + 0] + kk[j].x * delta;
                S[j * 4 + 1] = eg * S[j * 4 + 1] + kk[j].y * delta;
                S[j * 4 + 2] = eg * S[j * 4 + 2] + kk[j].z * delta;
                S[j * 4 + 3] = eg * S[j * 4 + 3] + kk[j].w * delta;
            }
        }
        prefetch(t + 6);
        prefetch(t + 7);
    }
}

// ================= gated RMSNorm (emits tf32-rounded xn) =================
__global__ __launch_bounds__(128)
void rmsnorm_kernel(const float* __restrict__ go, const float* __restrict__ qkvz,
                    const float* __restrict__ nw, float* __restrict__ gxn) {
    const int t = blockIdx.x, vh = blockIdx.y, i = threadIdx.x;
    __shared__ float red[4];
    const float o = go[(size_t)t * 2048 + vh * 128 + i];
    const float z = qkvz[(size_t)t * QKVZN + (vh >> 1) * 768 + 512 + (vh & 1) * 128 + i];
    const float xf = o * (z / (1.f + expf(-z)));
    float v = xf * xf;
#pragma unroll
    for (int m = 16; m; m >>= 1) v += __shfl_xor_sync(0xffffffffu, v, m);
    if ((i & 31) == 0) red[i >> 5] = v;
    __syncthreads();
    const float s = red[0] + red[1] + red[2] + red[3];
    gxn[(size_t)t * 2048 + vh * 128 + i] =
        to_tf32(xf * rsqrtf(s * (1.f / 128.f) + 1e-6f) * nw[i]);
}

// ================= launch =================
extern "C" void kernel_launch(void* const* d_in, const int* in_sizes, int n_in,
                              void* d_out, int out_size) {
    const float* hs      = (const float*)d_in[0];
    const float* w_qkvz  = (const float*)d_in[1];
    const float* w_ba    = (const float*)d_in[2];
    const float* conv_w  = (const float*)d_in[3];
    const float* dt_bias = (const float*)d_in[4];
    const float* A_log   = (const float*)d_in[5];
    const float* norm_w  = (const float*)d_in[6];
    const float* w_out   = (const float*)d_in[7];
    float* out = (float*)d_out;

    float *p_qkvz, *p_ba, *p_q, *p_k, *p_v, *p_qn, *p_kn, *p_scal, *p_o, *p_xn;
    float *p_hsr, *p_wqr, *p_wor;
    cudaGetSymbolAddress((void**)&p_qkvz, g_qkvz);
    cudaGetSymbolAddress((void**)&p_ba,   g_ba);
    cudaGetSymbolAddress((void**)&p_q,    g_q);
    cudaGetSymbolAddress((void**)&p_k,    g_k);
    cudaGetSymbolAddress((void**)&p_v,    g_v);
    cudaGetSymbolAddress((void**)&p_qn,   g_qn);
    cudaGetSymbolAddress((void**)&p_kn,   g_kn);
    cudaGetSymbolAddress((void**)&p_scal, g_scal);
    cudaGetSymbolAddress((void**)&p_o,    g_o);
    cudaGetSymbolAddress((void**)&p_xn,   g_xn);
    cudaGetSymbolAddress((void**)&p_hsr,  g_hsr);
    cudaGetSymbolAddress((void**)&p_wqr,  g_wqr);
    cudaGetSymbolAddress((void**)&p_wor,  g_wor);

    static int smem_set = 0;
    if (!smem_set) {
        cudaFuncSetAttribute(gemm_tf32_pipe, cudaFuncAttributeMaxDynamicSharedMemorySize,
                             GSTG * GSTF * 4);
        smem_set = 1;
    }

    // 0. tf32 pre-round of GEMM inputs
    round_tf32_k<<<1024, 256>>>((const float4*)hs,     (float4*)p_hsr, TLEN * HID / 4);
    round_tf32_k<<<2048, 256>>>((const float4*)w_qkvz, (float4*)p_wqr, QKVZN * HID / 4);
    round_tf32_k<<<2048, 256>>>((const float4*)w_out,  (float4*)p_wor, HID * HID / 4);
    // 1. qkvz projection [1024,6144]
    gemm_tf32_pipe<<<dim3(QKVZN / 128, TLEN / 128), 256, GSTG * GSTF * 4>>>(
        p_hsr, p_wqr, p_qkvz, QKVZN, HID);
    // 2. ba projection
    ba_kernel<<<TLEN, 256>>>(hs, w_ba, p_ba);
    // 3. conv + silu
    conv_kernel<<<dim3(32, 32), 256>>>(p_qkvz, conv_w, p_q, p_k, p_v);
    // 4. norm + gates
    prep_kernel<<<dim3(TLEN, NKH), 128>>>(p_q, p_k, p_ba, A_log, dt_bias, p_qn, p_kn, p_scal);
    // 5. delta-rule scan
    scan_kernel<<<dim3(8, NVH), 128>>>(p_qn, p_kn, p_v, p_scal, p_o);
    // 6. gated rmsnorm (tf32-rounded output)
    rmsnorm_kernel<<<dim3(TLEN, NVH), 128>>>(p_o, p_qkvz, norm_w, p_xn);
    // 7. output projection [1024,2048]
    gemm_tf32_pipe<<<dim3(HID / 128, TLEN / 128), 256, GSTG * GSTF * 4>>>(
        p_xn, p_wor, out, HID, HID);
}